// round 8
// baseline (speedup 1.0000x reference)
#include <cuda_runtime.h>
#include <cuda_fp16.h>
#include <math.h>
#include <stdint.h>

// ---------------------------------------------------------------------------
// Problem constants (B=1, S=4096, DIM=1536, HEADS=12, HEAD_DIM=128)
// ---------------------------------------------------------------------------
#define SEQ    4096
#define DIM    1536
#define NHEADS 12
#define HDIM   128
#define EPS    1e-6f

// Scratch (allocation-free rule: __device__ globals)
__device__ __half g_xh[SEQ * DIM];
__device__ __half g_qh[SEQ * DIM];
__device__ __half g_kh[SEQ * DIM];
__device__ __half g_vh[SEQ * DIM];
__device__ __half g_attnh[SEQ * DIM];
__device__ __half g_wqh[DIM * DIM];
__device__ __half g_wkh[DIM * DIM];
__device__ __half g_wvh[DIM * DIM];
__device__ __half g_woh[DIM * DIM];
__device__ __half g_vt[NHEADS * HDIM * SEQ];   // V transposed: [h][d][s]
__device__ float  g_trig[SEQ * 64 * 2];        // cos,sin per (pos, pair)

// ---------------------------------------------------------------------------
// Helpers
// ---------------------------------------------------------------------------
__device__ __forceinline__ unsigned ld32h(const __half* p) {
    return *(const unsigned*)p;
}

// D += A*B, m16n8k16, fp16 inputs, f32 accumulate
__device__ __forceinline__ void mma_f16(float* d, const unsigned* a,
                                        unsigned b0, unsigned b1) {
    asm volatile(
        "mma.sync.aligned.m16n8k16.row.col.f32.f16.f16.f32 "
        "{%0,%1,%2,%3}, {%4,%5,%6,%7}, {%8,%9}, {%0,%1,%2,%3};\n"
        : "+f"(d[0]), "+f"(d[1]), "+f"(d[2]), "+f"(d[3])
        : "r"(a[0]), "r"(a[1]), "r"(a[2]), "r"(a[3]), "r"(b0), "r"(b1));
}

// ---------------------------------------------------------------------------
// Prep: fp32 -> fp16, 5 segments in one launch (y: 0=x, 1..4=Wq,Wk,Wv,Wo)
// ---------------------------------------------------------------------------
__global__ __launch_bounds__(256) void to_half_all_kernel(
    const float* __restrict__ x,  const float* __restrict__ Wq,
    const float* __restrict__ Wk, const float* __restrict__ Wv,
    const float* __restrict__ Wo)
{
    const int seg = blockIdx.y;
    const float* src;
    __half* dst;
    int n4;
    if (seg == 0)      { src = x;  dst = g_xh;  n4 = SEQ * DIM / 4; }
    else if (seg == 1) { src = Wq; dst = g_wqh; n4 = DIM * DIM / 4; }
    else if (seg == 2) { src = Wk; dst = g_wkh; n4 = DIM * DIM / 4; }
    else if (seg == 3) { src = Wv; dst = g_wvh; n4 = DIM * DIM / 4; }
    else               { src = Wo; dst = g_woh; n4 = DIM * DIM / 4; }

    int i = blockIdx.x * blockDim.x + threadIdx.x;
    if (i >= n4) return;
    float4 v = ((const float4*)src)[i];
    __half2* d = (__half2*)dst;
    d[2 * i + 0] = __floats2half2_rn(v.x, v.y);
    d[2 * i + 1] = __floats2half2_rn(v.z, v.w);
}

// ---------------------------------------------------------------------------
// RoPE trig table with double-precision range reduction.
// ---------------------------------------------------------------------------
__global__ __launch_bounds__(256) void trig_kernel(const float* __restrict__ freqs) {
    int idx = blockIdx.x * blockDim.x + threadIdx.x;
    if (idx >= SEQ * 64) return;
    double a = (double)freqs[idx];
    double s, c;
    sincos(a, &s, &c);
    g_trig[idx * 2 + 0] = (float)c;
    g_trig[idx * 2 + 1] = (float)s;
}

// ---------------------------------------------------------------------------
// fp16 tensor-core GEMM, multi-output over blockIdx.z:
//   C_z[M,N] = A[M,K] @ W_z[N,K]^T + bias_z[N]
// BM=BN=128, BK=32, 256 threads (8 warps 4m x 2n), warp tile 32x64.
// Register-prefetch double buffer; smem stride 40 halfs (bank-conflict-free).
// ---------------------------------------------------------------------------
#define GSH 40

template <int HALF_OUT>
__global__ __launch_bounds__(256, 2) void gemm_h_kernel(
    const __half* __restrict__ A,
    const __half* __restrict__ W0, const __half* __restrict__ W1,
    const __half* __restrict__ W2,
    const float* __restrict__ b0p, const float* __restrict__ b1p,
    const float* __restrict__ b2p,
    void* C0, void* C1, void* C2)
{
    __shared__ __half As[2][128 * GSH];
    __shared__ __half Ws[2][128 * GSH];

    const int z = blockIdx.z;
    const __half* W   = (z == 0) ? W0  : (z == 1) ? W1  : W2;
    const float* bias = (z == 0) ? b0p : (z == 1) ? b1p : b2p;
    void* C           = (z == 0) ? C0  : (z == 1) ? C1  : C2;

    const int t    = threadIdx.x;
    const int lane = t & 31;
    const int warp = t >> 5;
    const int wm   = warp >> 1;     // 0..3
    const int wn   = warp & 1;      // 0..1
    const int bm   = blockIdx.y * 128;
    const int bn   = blockIdx.x * 128;

    const int lrow = t >> 1;            // 0..127
    const int lc   = (t & 1) * 16;      // 0 or 16 (halfs)

    const __half* Ap = A + (size_t)(bm + lrow) * DIM + lc;
    const __half* Wp = W + (size_t)(bn + lrow) * DIM + lc;

    float c[2][8][4];
#pragma unroll
    for (int mt = 0; mt < 2; mt++)
#pragma unroll
        for (int nt = 0; nt < 8; nt++)
#pragma unroll
            for (int j = 0; j < 4; j++) c[mt][nt][j] = 0.f;

    const int KITERS = DIM / 32;   // 48

    uint4 pa0 = *(const uint4*)Ap;
    uint4 pa1 = *(const uint4*)(Ap + 8);
    uint4 pw0 = *(const uint4*)Wp;
    uint4 pw1 = *(const uint4*)(Wp + 8);
    *(uint4*)&As[0][lrow * GSH + lc]     = pa0;
    *(uint4*)&As[0][lrow * GSH + lc + 8] = pa1;
    *(uint4*)&Ws[0][lrow * GSH + lc]     = pw0;
    *(uint4*)&Ws[0][lrow * GSH + lc + 8] = pw1;
    __syncthreads();

    const int r0  = lane >> 2;
    const int kq  = lane & 3;
    const int r_a = wm * 32 + r0;
    const int r_b = wn * 64 + r0;

    for (int it = 0; it < KITERS; ++it) {
        const int cur = it & 1;
        if (it + 1 < KITERS) {
            const __half* ap = Ap + (it + 1) * 32;
            const __half* wp = Wp + (it + 1) * 32;
            pa0 = *(const uint4*)ap;
            pa1 = *(const uint4*)(ap + 8);
            pw0 = *(const uint4*)wp;
            pw1 = *(const uint4*)(wp + 8);
        }

        const __half* as = As[cur];
        const __half* ws = Ws[cur];

#pragma unroll
        for (int kt = 0; kt < 2; ++kt) {
            const int kc = kt * 16 + 2 * kq;
            unsigned a[2][4];
#pragma unroll
            for (int mt = 0; mt < 2; ++mt) {
                int r = r_a + mt * 16;
                a[mt][0] = ld32h(&as[r * GSH + kc]);
                a[mt][1] = ld32h(&as[(r + 8) * GSH + kc]);
                a[mt][2] = ld32h(&as[r * GSH + kc + 8]);
                a[mt][3] = ld32h(&as[(r + 8) * GSH + kc + 8]);
            }
#pragma unroll
            for (int nt = 0; nt < 8; ++nt) {
                int n = r_b + nt * 8;
                unsigned bb0 = ld32h(&ws[n * GSH + kc]);
                unsigned bb1 = ld32h(&ws[n * GSH + kc + 8]);
                mma_f16(c[0][nt], a[0], bb0, bb1);
                mma_f16(c[1][nt], a[1], bb0, bb1);
            }
        }

        if (it + 1 < KITERS) {
            *(uint4*)&As[cur ^ 1][lrow * GSH + lc]     = pa0;
            *(uint4*)&As[cur ^ 1][lrow * GSH + lc + 8] = pa1;
            *(uint4*)&Ws[cur ^ 1][lrow * GSH + lc]     = pw0;
            *(uint4*)&Ws[cur ^ 1][lrow * GSH + lc + 8] = pw1;
        }
        __syncthreads();
    }

    // Epilogue: bias + store
#pragma unroll
    for (int mt = 0; mt < 2; ++mt) {
#pragma unroll
        for (int nt = 0; nt < 8; ++nt) {
            int row = bm + wm * 32 + mt * 16 + r0;
            int col = bn + wn * 64 + nt * 8 + 2 * kq;
            float bb0 = bias[col], bb1 = bias[col + 1];
            float v0 = c[mt][nt][0] + bb0, v1 = c[mt][nt][1] + bb1;
            float v2 = c[mt][nt][2] + bb0, v3 = c[mt][nt][3] + bb1;
            if (HALF_OUT) {
                __half2* Ch = (__half2*)C;
                Ch[((size_t)row * DIM + col) >> 1]       = __floats2half2_rn(v0, v1);
                Ch[((size_t)(row + 8) * DIM + col) >> 1] = __floats2half2_rn(v2, v3);
            } else {
                float* Cf = (float*)C;
                *(float2*)&Cf[(size_t)row * DIM + col]       = make_float2(v0, v1);
                *(float2*)&Cf[(size_t)(row + 8) * DIM + col] = make_float2(v2, v3);
            }
        }
    }
}

// ---------------------------------------------------------------------------
// Fused RMSNorm + RoPE for q AND k (fp16 in/out, fp32 math): grid (SEQ, 2).
// ---------------------------------------------------------------------------
__global__ __launch_bounds__(256) void rmsnorm_rope_kernel(
    __half* __restrict__ Xq, __half* __restrict__ Xk,
    const float* __restrict__ gqv, const float* __restrict__ gkv)
{
    __shared__ float sh[DIM];
    __shared__ float red[8];
    __shared__ float s_r;

    const int s = blockIdx.x;
    const int which = blockIdx.y;
    __half* X = which ? Xk : Xq;
    const float* g = which ? gkv : gqv;

    const int t = threadIdx.x;
    __half2* row = (__half2*)(X + (size_t)s * DIM);

    float ss = 0.f;
    for (int i = t; i < DIM / 2; i += 256) {
        float2 f = __half22float2(row[i]);
        sh[2 * i]     = f.x;
        sh[2 * i + 1] = f.y;
        ss += f.x * f.x + f.y * f.y;
    }
#pragma unroll
    for (int off = 16; off > 0; off >>= 1)
        ss += __shfl_xor_sync(0xFFFFFFFFu, ss, off);
    if ((t & 31) == 0) red[t >> 5] = ss;
    __syncthreads();
    if (t == 0) {
        float tot = 0.f;
#pragma unroll
        for (int w = 0; w < 8; w++) tot += red[w];
        s_r = rsqrtf(tot / (float)DIM + EPS);
    }
    __syncthreads();
    const float r = s_r;

    for (int p = t; p < DIM / 2; p += 256) {
        int j = p & 63;
        float c  = g_trig[((size_t)s * 64 + j) * 2 + 0];
        float sn = g_trig[((size_t)s * 64 + j) * 2 + 1];
        float v0 = sh[2 * p] * r * g[2 * p];
        float v1 = sh[2 * p + 1] * r * g[2 * p + 1];
        row[p] = __floats2half2_rn(v0 * c - v1 * sn, v0 * sn + v1 * c);
    }
}

// ---------------------------------------------------------------------------
// Transpose V: g_vh[s][h*128+d] -> g_vt[h][d][s].  Tiles 64s x 64d.
// ---------------------------------------------------------------------------
__global__ __launch_bounds__(256) void transpose_v_kernel(void) {
    __shared__ __half tile[64][80];
    const int t  = threadIdx.x;
    const int h  = blockIdx.y >> 1;
    const int d0 = (blockIdx.y & 1) * 64;
    const int s0 = blockIdx.x * 64;

    for (int i = t; i < 512; i += 256) {
        int r = i >> 3, c8 = (i & 7) * 8;
        uint4 v = *(const uint4*)&g_vh[(size_t)(s0 + r) * DIM + h * HDIM + d0 + c8];
        *(uint4*)&tile[r][c8] = v;
    }
    __syncthreads();
    for (int i = t; i < 512; i += 256) {
        int r = i >> 3, c8 = (i & 7) * 8;
        __half tmp[8];
#pragma unroll
        for (int j = 0; j < 8; ++j) tmp[j] = tile[c8 + j][r];
        *(uint4*)&g_vt[(size_t)(h * HDIM + d0 + r) * SEQ + s0 + c8] = *(uint4*)tmp;
    }
}

// ---------------------------------------------------------------------------
// fp16 flash attention. 256 threads (8 warps), BQ=128 (16 rows/warp), BK=64.
// Each staged K/V tile feeds 128 q rows (2x reuse vs BQ=64).
// Q fragments in registers. fp32 softmax + O accumulators. fp16 output.
// ---------------------------------------------------------------------------
#define KSH 136
#define VSH 72
#define PSH 72
#define FA_SMEM_BYTES ((64 * KSH + 128 * VSH + 128 * PSH) * 2)   // 54272

__global__ __launch_bounds__(256) void flash_h_kernel(
    const __half* __restrict__ Q, const __half* __restrict__ Kg,
    const __half* __restrict__ Vt, __half* __restrict__ O)
{
    extern __shared__ __half smh[];
    __half* Ks = smh;                    // 64 x 136
    __half* Vs = Ks + 64 * KSH;          // 128 x 72 (d-major)
    __half* Ps = Vs + 128 * VSH;         // 128 x 72

    const int h    = blockIdx.y;
    const int qb   = blockIdx.x;
    const int t    = threadIdx.x;
    const int lane = t & 31;
    const int warp = t >> 5;             // 0..7
    const int r0   = lane >> 2;
    const int qc   = lane & 3;
    const int prow = warp * 16 + r0;     // 0..127
    const float scale = 0.08838834764831845f;   // 1/sqrt(128)

    // ---- Stage full Q tile [128 rows x 128 d] across Ks+Vs region ----
    {
        const __half* src = Q + (size_t)(qb * 128) * DIM + h * HDIM;
        for (int i = t; i < 128 * 16; i += 256) {
            int r = i >> 4, c8 = (i & 15) * 8;
            *(uint4*)&smh[r * KSH + c8] = *(const uint4*)&src[(size_t)r * DIM + c8];
        }
    }
    __syncthreads();

    unsigned qa[8][4];
#pragma unroll
    for (int kt = 0; kt < 8; ++kt) {
        int kc = kt * 16 + 2 * qc;
        qa[kt][0] = ld32h(&smh[prow * KSH + kc]);
        qa[kt][1] = ld32h(&smh[(prow + 8) * KSH + kc]);
        qa[kt][2] = ld32h(&smh[prow * KSH + kc + 8]);
        qa[kt][3] = ld32h(&smh[(prow + 8) * KSH + kc + 8]);
    }
    __syncthreads();

    float o[16][4];
#pragma unroll
    for (int nt = 0; nt < 16; ++nt)
#pragma unroll
        for (int j = 0; j < 4; ++j) o[nt][j] = 0.f;

    float m0 = -1e30f, m1 = -1e30f, l0 = 0.f, l1 = 0.f;

    for (int kb = 0; kb < SEQ / 64; ++kb) {
        __syncthreads();

        // ---- Stage K tile [64 keys][128 d] and Vt tile [128 d][64 keys] ----
        {
            const __half* ksrc = Kg + (size_t)(kb * 64) * DIM + h * HDIM;
            for (int i = t; i < 64 * 16; i += 256) {
                int r = i >> 4, c8 = (i & 15) * 8;
                *(uint4*)&Ks[r * KSH + c8] = *(const uint4*)&ksrc[(size_t)r * DIM + c8];
            }
            const __half* vsrc = Vt + (size_t)h * HDIM * SEQ + kb * 64;
            for (int i = t; i < 128 * 8; i += 256) {
                int r = i >> 3, c8 = (i & 7) * 8;
                *(uint4*)&Vs[r * VSH + c8] = *(const uint4*)&vsrc[(size_t)r * SEQ + c8];
            }
        }
        __syncthreads();

        // ---- S = Q @ K^T (per warp: 16 x 64) ----
        float s[8][4];
#pragma unroll
        for (int nt = 0; nt < 8; ++nt)
#pragma unroll
            for (int j = 0; j < 4; ++j) s[nt][j] = 0.f;

#pragma unroll
        for (int nt = 0; nt < 8; ++nt) {
            const int nb = (nt * 8 + r0) * KSH + 2 * qc;
#pragma unroll
            for (int kt = 0; kt < 8; ++kt) {
                unsigned b0 = ld32h(&Ks[nb + kt * 16]);
                unsigned b1 = ld32h(&Ks[nb + kt * 16 + 8]);
                mma_f16(s[nt], qa[kt], b0, b1);
            }
        }

        // ---- Online softmax ----
        float mx0 = -1e30f, mx1 = -1e30f;
#pragma unroll
        for (int nt = 0; nt < 8; ++nt) {
            mx0 = fmaxf(mx0, fmaxf(s[nt][0], s[nt][1]));
            mx1 = fmaxf(mx1, fmaxf(s[nt][2], s[nt][3]));
        }
        mx0 = fmaxf(mx0, __shfl_xor_sync(0xFFFFFFFFu, mx0, 1));
        mx0 = fmaxf(mx0, __shfl_xor_sync(0xFFFFFFFFu, mx0, 2));
        mx1 = fmaxf(mx1, __shfl_xor_sync(0xFFFFFFFFu, mx1, 1));
        mx1 = fmaxf(mx1, __shfl_xor_sync(0xFFFFFFFFu, mx1, 2));

        float nm0 = fmaxf(m0, mx0 * scale);
        float nm1 = fmaxf(m1, mx1 * scale);
        float corr0 = __expf(m0 - nm0);
        float corr1 = __expf(m1 - nm1);

        float sum0 = 0.f, sum1 = 0.f;
#pragma unroll
        for (int nt = 0; nt < 8; ++nt) {
            s[nt][0] = __expf(s[nt][0] * scale - nm0);
            s[nt][1] = __expf(s[nt][1] * scale - nm0);
            s[nt][2] = __expf(s[nt][2] * scale - nm1);
            s[nt][3] = __expf(s[nt][3] * scale - nm1);
            sum0 += s[nt][0] + s[nt][1];
            sum1 += s[nt][2] + s[nt][3];
        }
        sum0 += __shfl_xor_sync(0xFFFFFFFFu, sum0, 1);
        sum0 += __shfl_xor_sync(0xFFFFFFFFu, sum0, 2);
        sum1 += __shfl_xor_sync(0xFFFFFFFFu, sum1, 1);
        sum1 += __shfl_xor_sync(0xFFFFFFFFu, sum1, 2);

        l0 = l0 * corr0 + sum0;
        l1 = l1 * corr1 + sum1;
        m0 = nm0;
        m1 = nm1;

#pragma unroll
        for (int nt = 0; nt < 16; ++nt) {
            o[nt][0] *= corr0; o[nt][1] *= corr0;
            o[nt][2] *= corr1; o[nt][3] *= corr1;
        }

        // ---- P -> smem fp16 (warp-local rows) ----
#pragma unroll
        for (int nt = 0; nt < 8; ++nt) {
            int pc = nt * 8 + 2 * qc;
            *(__half2*)&Ps[prow * PSH + pc] = __floats2half2_rn(s[nt][0], s[nt][1]);
            *(__half2*)&Ps[(prow + 8) * PSH + pc] = __floats2half2_rn(s[nt][2], s[nt][3]);
        }
        __syncwarp();

        // ---- O += P @ V (Vt d-major: each B-frag = one LDS.32) ----
#pragma unroll
        for (int kt = 0; kt < 4; ++kt) {
            unsigned a[4];
            int kc = kt * 16 + 2 * qc;
            a[0] = ld32h(&Ps[prow * PSH + kc]);
            a[1] = ld32h(&Ps[(prow + 8) * PSH + kc]);
            a[2] = ld32h(&Ps[prow * PSH + kc + 8]);
            a[3] = ld32h(&Ps[(prow + 8) * PSH + kc + 8]);
#pragma unroll
            for (int nt = 0; nt < 16; ++nt) {
                const int nb = (nt * 8 + r0) * VSH + kt * 16 + 2 * qc;
                unsigned b0 = ld32h(&Vs[nb]);
                unsigned b1 = ld32h(&Vs[nb + 8]);
                mma_f16(o[nt], a, b0, b1);
            }
        }
    }

    // ---- Epilogue: normalize, fp16 store ----
    float inv0 = 1.f / l0, inv1 = 1.f / l1;
    int grow = qb * 128 + prow;
#pragma unroll
    for (int nt = 0; nt < 16; ++nt) {
        int col = h * HDIM + nt * 8 + 2 * qc;
        *(__half2*)&O[(size_t)grow * DIM + col] =
            __floats2half2_rn(o[nt][0] * inv0, o[nt][1] * inv0);
        *(__half2*)&O[(size_t)(grow + 8) * DIM + col] =
            __floats2half2_rn(o[nt][2] * inv1, o[nt][3] * inv1);
    }
}

// ---------------------------------------------------------------------------
// Launch
// ---------------------------------------------------------------------------
extern "C" void kernel_launch(void* const* d_in, const int* in_sizes, int n_in,
                              void* d_out, int out_size)
{
    const float* x     = (const float*)d_in[0];
    const float* freqs = (const float*)d_in[1];
    const float* Wq    = (const float*)d_in[2];
    const float* bq    = (const float*)d_in[3];
    const float* Wk    = (const float*)d_in[4];
    const float* bk    = (const float*)d_in[5];
    const float* Wv    = (const float*)d_in[6];
    const float* bv    = (const float*)d_in[7];
    const float* Wo    = (const float*)d_in[8];
    const float* bo    = (const float*)d_in[9];
    const float* gq    = (const float*)d_in[10];
    const float* gk    = (const float*)d_in[11];
    float* out = (float*)d_out;

    __half *xh, *qh, *kh, *vh, *attnh, *wqh, *wkh, *wvh, *woh, *vt;
    cudaGetSymbolAddress((void**)&xh,    g_xh);
    cudaGetSymbolAddress((void**)&qh,    g_qh);
    cudaGetSymbolAddress((void**)&kh,    g_kh);
    cudaGetSymbolAddress((void**)&vh,    g_vh);
    cudaGetSymbolAddress((void**)&attnh, g_attnh);
    cudaGetSymbolAddress((void**)&wqh,   g_wqh);
    cudaGetSymbolAddress((void**)&wkh,   g_wkh);
    cudaGetSymbolAddress((void**)&wvh,   g_wvh);
    cudaGetSymbolAddress((void**)&woh,   g_woh);
    cudaGetSymbolAddress((void**)&vt,    g_vt);

    cudaFuncSetAttribute(flash_h_kernel,
                         cudaFuncAttributeMaxDynamicSharedMemorySize, FA_SMEM_BYTES);

    // Prep: trig + fp16 conversion (single fused launch).
    trig_kernel<<<(SEQ * 64 + 255) / 256, 256>>>(freqs);
    to_half_all_kernel<<<dim3(SEQ * DIM / 4 / 256, 5), 256>>>(x, Wq, Wk, Wv, Wo);

    // Fused Q/K/V projection (fp16 in/out).
    dim3 qkv_grid(DIM / 128, SEQ / 128, 3);
    gemm_h_kernel<1><<<qkv_grid, 256>>>(
        xh, wqh, wkh, wvh, bq, bk, bv, qh, kh, vh);

    // RMSNorm+RoPE for q and k.
    rmsnorm_rope_kernel<<<dim3(SEQ, 2), 256>>>(qh, kh, gq, gk);

    // Transpose V for the PV GEMM.
    transpose_v_kernel<<<dim3(SEQ / 64, 2 * NHEADS), 256>>>();

    // Flash attention: BQ=128, 8 warps.
    flash_h_kernel<<<dim3(SEQ / 128, NHEADS), 256, FA_SMEM_BYTES>>>(qh, kh, vt, attnh);

    // Output projection (fp32 out).
    dim3 o_grid(DIM / 128, SEQ / 128, 1);
    gemm_h_kernel<0><<<o_grid, 256>>>(
        attnh, woh, woh, woh, bo, bo, bo, out, out, out);
}

// round 10
// speedup vs baseline: 1.1746x; 1.1746x over previous
#include <cuda_runtime.h>
#include <cuda_fp16.h>
#include <math.h>
#include <stdint.h>

// ---------------------------------------------------------------------------
// Problem constants (B=1, S=4096, DIM=1536, HEADS=12, HEAD_DIM=128)
// ---------------------------------------------------------------------------
#define SEQ    4096
#define DIM    1536
#define NHEADS 12
#define HDIM   128
#define EPS    1e-6f

// Scratch (allocation-free rule: __device__ globals)
__device__ __half g_xh[SEQ * DIM];
__device__ __half g_qh[SEQ * DIM];
__device__ __half g_kh[SEQ * DIM];
__device__ __half g_vh[SEQ * DIM];
__device__ __half g_attnh[SEQ * DIM];
__device__ __half g_wqh[DIM * DIM];
__device__ __half g_wkh[DIM * DIM];
__device__ __half g_wvh[DIM * DIM];
__device__ __half g_woh[DIM * DIM];
__device__ __half g_vt[NHEADS * HDIM * SEQ];   // V transposed: [h][d][s]
__device__ float  g_trig[SEQ * 64 * 2];        // cos,sin per (pos, pair)

// ---------------------------------------------------------------------------
// Helpers
// ---------------------------------------------------------------------------
__device__ __forceinline__ unsigned ld32h(const __half* p) {
    return *(const unsigned*)p;
}

// D += A*B, m16n8k16, fp16 inputs, f32 accumulate
__device__ __forceinline__ void mma_f16(float* d, const unsigned* a,
                                        unsigned b0, unsigned b1) {
    asm volatile(
        "mma.sync.aligned.m16n8k16.row.col.f32.f16.f16.f32 "
        "{%0,%1,%2,%3}, {%4,%5,%6,%7}, {%8,%9}, {%0,%1,%2,%3};\n"
        : "+f"(d[0]), "+f"(d[1]), "+f"(d[2]), "+f"(d[3])
        : "r"(a[0]), "r"(a[1]), "r"(a[2]), "r"(a[3]), "r"(b0), "r"(b1));
}

// ---------------------------------------------------------------------------
// Prep: fp32 -> fp16, 5 segments in one launch (y: 0=x, 1..4=Wq,Wk,Wv,Wo)
// ---------------------------------------------------------------------------
__global__ __launch_bounds__(256) void to_half_all_kernel(
    const float* __restrict__ x,  const float* __restrict__ Wq,
    const float* __restrict__ Wk, const float* __restrict__ Wv,
    const float* __restrict__ Wo)
{
    const int seg = blockIdx.y;
    const float* src;
    __half* dst;
    int n4;
    if (seg == 0)      { src = x;  dst = g_xh;  n4 = SEQ * DIM / 4; }
    else if (seg == 1) { src = Wq; dst = g_wqh; n4 = DIM * DIM / 4; }
    else if (seg == 2) { src = Wk; dst = g_wkh; n4 = DIM * DIM / 4; }
    else if (seg == 3) { src = Wv; dst = g_wvh; n4 = DIM * DIM / 4; }
    else               { src = Wo; dst = g_woh; n4 = DIM * DIM / 4; }

    int i = blockIdx.x * blockDim.x + threadIdx.x;
    if (i >= n4) return;
    float4 v = ((const float4*)src)[i];
    __half2* d = (__half2*)dst;
    d[2 * i + 0] = __floats2half2_rn(v.x, v.y);
    d[2 * i + 1] = __floats2half2_rn(v.z, v.w);
}

// ---------------------------------------------------------------------------
// RoPE trig table with double-precision range reduction.
// ---------------------------------------------------------------------------
__global__ __launch_bounds__(256) void trig_kernel(const float* __restrict__ freqs) {
    int idx = blockIdx.x * blockDim.x + threadIdx.x;
    if (idx >= SEQ * 64) return;
    double a = (double)freqs[idx];
    double s, c;
    sincos(a, &s, &c);
    g_trig[idx * 2 + 0] = (float)c;
    g_trig[idx * 2 + 1] = (float)s;
}

// ---------------------------------------------------------------------------
// fp16 tensor-core GEMM, multi-output over blockIdx.z (R7 structure):
//   C_z[M,N] = A[M,K] @ W_z[N,K]^T + bias_z[N]
// BM=BN=128, BK=16, 256 threads (8 warps 4m x 2n), warp tile 32x64.
// Register-prefetch double buffer; smem stride 24 halfs (bank-conflict-free).
// ---------------------------------------------------------------------------
#define GSH 24

template <int HALF_OUT>
__global__ __launch_bounds__(256, 2) void gemm_h_kernel(
    const __half* __restrict__ A,
    const __half* __restrict__ W0, const __half* __restrict__ W1,
    const __half* __restrict__ W2,
    const float* __restrict__ b0p, const float* __restrict__ b1p,
    const float* __restrict__ b2p,
    void* C0, void* C1, void* C2)
{
    __shared__ __align__(16) __half As[2][128 * GSH];
    __shared__ __align__(16) __half Ws[2][128 * GSH];

    const int z = blockIdx.z;
    const __half* W   = (z == 0) ? W0  : (z == 1) ? W1  : W2;
    const float* bias = (z == 0) ? b0p : (z == 1) ? b1p : b2p;
    void* C           = (z == 0) ? C0  : (z == 1) ? C1  : C2;

    const int t    = threadIdx.x;
    const int lane = t & 31;
    const int warp = t >> 5;
    const int wm   = warp >> 1;     // 0..3
    const int wn   = warp & 1;      // 0..1
    const int bm   = blockIdx.y * 128;
    const int bn   = blockIdx.x * 128;

    const int lrow = t >> 1;            // 0..127
    const int lc8  = (t & 1) * 8;       // 0 or 8

    const __half* Ap = A + (size_t)(bm + lrow) * DIM + lc8;
    const __half* Wp = W + (size_t)(bn + lrow) * DIM + lc8;

    float c[2][8][4];
#pragma unroll
    for (int mt = 0; mt < 2; mt++)
#pragma unroll
        for (int nt = 0; nt < 8; nt++)
#pragma unroll
            for (int j = 0; j < 4; j++) c[mt][nt][j] = 0.f;

    const int KITERS = DIM / 16;   // 96

    uint4 pa = *(const uint4*)Ap;
    uint4 pw = *(const uint4*)Wp;
    *(uint4*)&As[0][lrow * GSH + lc8] = pa;
    *(uint4*)&Ws[0][lrow * GSH + lc8] = pw;
    __syncthreads();

    const int r0  = lane >> 2;
    const int kq  = lane & 3;
    const int r_a = wm * 32 + r0;
    const int r_b = wn * 64 + r0;

    for (int it = 0; it < KITERS; ++it) {
        const int cur = it & 1;
        if (it + 1 < KITERS) {
            pa = *(const uint4*)(Ap + (it + 1) * 16);
            pw = *(const uint4*)(Wp + (it + 1) * 16);
        }

        const __half* as = As[cur];
        const __half* ws = Ws[cur];

        unsigned a[2][4];
#pragma unroll
        for (int mt = 0; mt < 2; ++mt) {
            int r = r_a + mt * 16;
            a[mt][0] = ld32h(&as[r * GSH + 2 * kq]);
            a[mt][1] = ld32h(&as[(r + 8) * GSH + 2 * kq]);
            a[mt][2] = ld32h(&as[r * GSH + 2 * kq + 8]);
            a[mt][3] = ld32h(&as[(r + 8) * GSH + 2 * kq + 8]);
        }
#pragma unroll
        for (int nt = 0; nt < 8; ++nt) {
            int n = r_b + nt * 8;
            unsigned bb0 = ld32h(&ws[n * GSH + 2 * kq]);
            unsigned bb1 = ld32h(&ws[n * GSH + 2 * kq + 8]);
            mma_f16(c[0][nt], a[0], bb0, bb1);
            mma_f16(c[1][nt], a[1], bb0, bb1);
        }

        if (it + 1 < KITERS) {
            *(uint4*)&As[cur ^ 1][lrow * GSH + lc8] = pa;
            *(uint4*)&Ws[cur ^ 1][lrow * GSH + lc8] = pw;
        }
        __syncthreads();
    }

    // Epilogue: bias + store
#pragma unroll
    for (int mt = 0; mt < 2; ++mt) {
#pragma unroll
        for (int nt = 0; nt < 8; ++nt) {
            int row = bm + wm * 32 + mt * 16 + r0;
            int col = bn + wn * 64 + nt * 8 + 2 * kq;
            float bb0 = bias[col], bb1 = bias[col + 1];
            float v0 = c[mt][nt][0] + bb0, v1 = c[mt][nt][1] + bb1;
            float v2 = c[mt][nt][2] + bb0, v3 = c[mt][nt][3] + bb1;
            if (HALF_OUT) {
                __half2* Ch = (__half2*)C;
                Ch[((size_t)row * DIM + col) >> 1]       = __floats2half2_rn(v0, v1);
                Ch[((size_t)(row + 8) * DIM + col) >> 1] = __floats2half2_rn(v2, v3);
            } else {
                float* Cf = (float*)C;
                *(float2*)&Cf[(size_t)row * DIM + col]       = make_float2(v0, v1);
                *(float2*)&Cf[(size_t)(row + 8) * DIM + col] = make_float2(v2, v3);
            }
        }
    }
}

// ---------------------------------------------------------------------------
// Fused RMSNorm+RoPE (y=0: q, y=1: k) AND V-transpose (y=2) in ONE launch.
// Shared buffers OVERLAY in a 16-byte-aligned union (the two paths never
// coexist in a block) — this fixes R9's misaligned-address crash where a
// separately-declared __half tile landed on a non-16B boundary.
// ---------------------------------------------------------------------------
struct __align__(16) NTShared {
    union {
        struct {
            float sh[DIM];
            float red[8];
            float s_r;
        } n;
        __half tile[64][80];   // 10240 bytes < sizeof(n)=6180? No: take max
    } u;
};

__global__ __launch_bounds__(256) void norm_and_transpose_kernel(
    __half* __restrict__ Xq, __half* __restrict__ Xk,
    const float* __restrict__ gqv, const float* __restrict__ gkv)
{
    __shared__ NTShared S;

    const int t = threadIdx.x;

    if (blockIdx.y == 2) {
        // ---- V transpose: g_vh[s][h*128+d] -> g_vt[h][d][s] ----
        const int bx = blockIdx.x;
        if (bx >= (SEQ / 64) * 2 * NHEADS) return;
        const int sblk = bx % (SEQ / 64);
        const int hz   = bx / (SEQ / 64);       // 0..23
        const int h    = hz >> 1;
        const int d0   = (hz & 1) * 64;
        const int s0   = sblk * 64;

        for (int i = t; i < 512; i += 256) {
            int r = i >> 3, c8 = (i & 7) * 8;
            uint4 v = *(const uint4*)&g_vh[(size_t)(s0 + r) * DIM + h * HDIM + d0 + c8];
            *(uint4*)&S.u.tile[r][c8] = v;
        }
        __syncthreads();
        for (int i = t; i < 512; i += 256) {
            int r = i >> 3, c8 = (i & 7) * 8;
            __half tmp[8];
#pragma unroll
            for (int j = 0; j < 8; ++j) tmp[j] = S.u.tile[c8 + j][r];
            *(uint4*)&g_vt[(size_t)(h * HDIM + d0 + r) * SEQ + s0 + c8] = *(uint4*)tmp;
        }
        return;
    }

    // ---- RMSNorm + RoPE ----
    const int s = blockIdx.x;
    const int which = blockIdx.y;
    __half* X = which ? Xk : Xq;
    const float* g = which ? gkv : gqv;

    __half2* row = (__half2*)(X + (size_t)s * DIM);

    float ss = 0.f;
    for (int i = t; i < DIM / 2; i += 256) {
        float2 f = __half22float2(row[i]);
        S.u.n.sh[2 * i]     = f.x;
        S.u.n.sh[2 * i + 1] = f.y;
        ss += f.x * f.x + f.y * f.y;
    }
#pragma unroll
    for (int off = 16; off > 0; off >>= 1)
        ss += __shfl_xor_sync(0xFFFFFFFFu, ss, off);
    if ((t & 31) == 0) S.u.n.red[t >> 5] = ss;
    __syncthreads();
    if (t == 0) {
        float tot = 0.f;
#pragma unroll
        for (int w = 0; w < 8; w++) tot += S.u.n.red[w];
        S.u.n.s_r = rsqrtf(tot / (float)DIM + EPS);
    }
    __syncthreads();
    const float r = S.u.n.s_r;

    for (int p = t; p < DIM / 2; p += 256) {
        int j = p & 63;
        float c  = g_trig[((size_t)s * 64 + j) * 2 + 0];
        float sn = g_trig[((size_t)s * 64 + j) * 2 + 1];
        float v0 = S.u.n.sh[2 * p] * r * g[2 * p];
        float v1 = S.u.n.sh[2 * p + 1] * r * g[2 * p + 1];
        row[p] = __floats2half2_rn(v0 * c - v1 * sn, v0 * sn + v1 * c);
    }
}

// ---------------------------------------------------------------------------
// fp16 flash attention (R7 structure — measured best).
// 128 threads (4 warps), BQ=64 (16 rows/warp), BK=64.
// Q fragments in registers. K natural [key][d]; V via Vt [d][key].
// fp32 softmax and O accumulators. Output fp16.
// ---------------------------------------------------------------------------
#define KSH 136
#define VSH 72
#define PSH 72
#define FA_SMEM_BYTES ((64 * KSH + 128 * VSH + 64 * PSH) * 2)   // 45056

__global__ __launch_bounds__(128, 2) void flash_h_kernel(
    const __half* __restrict__ Q, const __half* __restrict__ Kg,
    const __half* __restrict__ Vt, __half* __restrict__ O)
{
    extern __shared__ __align__(16) __half smh[];
    __half* Ks = smh;                    // 64 x 136
    __half* Vs = Ks + 64 * KSH;          // 128 x 72 (d-major)
    __half* Ps = Vs + 128 * VSH;         // 64 x 72

    const int h    = blockIdx.y;
    const int qb   = blockIdx.x;
    const int t    = threadIdx.x;
    const int lane = t & 31;
    const int warp = t >> 5;
    const int r0   = lane >> 2;
    const int qc   = lane & 3;
    const float scale = 0.08838834764831845f;   // 1/sqrt(128)

    // ---- Stage Q tile into Ks, pull A-fragments to registers ----
    {
        const __half* src = Q + (size_t)(qb * 64) * DIM + h * HDIM;
        for (int i = t; i < 64 * 16; i += 128) {
            int r = i >> 4, c8 = (i & 15) * 8;
            *(uint4*)&Ks[r * KSH + c8] = *(const uint4*)&src[(size_t)r * DIM + c8];
        }
    }
    __syncthreads();

    unsigned qa[8][4];
    {
        const int rb = warp * 16 + r0;
#pragma unroll
        for (int kt = 0; kt < 8; ++kt) {
            int kc = kt * 16 + 2 * qc;
            qa[kt][0] = ld32h(&Ks[rb * KSH + kc]);
            qa[kt][1] = ld32h(&Ks[(rb + 8) * KSH + kc]);
            qa[kt][2] = ld32h(&Ks[rb * KSH + kc + 8]);
            qa[kt][3] = ld32h(&Ks[(rb + 8) * KSH + kc + 8]);
        }
    }
    __syncthreads();

    float o[16][4];
#pragma unroll
    for (int nt = 0; nt < 16; ++nt)
#pragma unroll
        for (int j = 0; j < 4; ++j) o[nt][j] = 0.f;

    float m0 = -1e30f, m1 = -1e30f, l0 = 0.f, l1 = 0.f;
    const int prow = warp * 16 + r0;

    for (int kb = 0; kb < SEQ / 64; ++kb) {
        __syncthreads();

        // ---- Stage K tile [64 keys][128 d] and Vt tile [128 d][64 keys] ----
        {
            const __half* ksrc = Kg + (size_t)(kb * 64) * DIM + h * HDIM;
            for (int i = t; i < 64 * 16; i += 128) {
                int r = i >> 4, c8 = (i & 15) * 8;
                *(uint4*)&Ks[r * KSH + c8] = *(const uint4*)&ksrc[(size_t)r * DIM + c8];
            }
            const __half* vsrc = Vt + (size_t)h * HDIM * SEQ + kb * 64;
            for (int i = t; i < 128 * 16; i += 128) {
                int r = i >> 4, c4 = (i & 15) * 4;
                *(uint2*)&Vs[r * VSH + c4] = *(const uint2*)&vsrc[(size_t)r * SEQ + c4];
            }
        }
        __syncthreads();

        // ---- S = Q @ K^T (per warp: 16 x 64) ----
        float s[8][4];
#pragma unroll
        for (int nt = 0; nt < 8; ++nt)
#pragma unroll
            for (int j = 0; j < 4; ++j) s[nt][j] = 0.f;

#pragma unroll
        for (int nt = 0; nt < 8; ++nt) {
            const int nb = (nt * 8 + r0) * KSH + 2 * qc;
#pragma unroll
            for (int kt = 0; kt < 8; ++kt) {
                unsigned b0 = ld32h(&Ks[nb + kt * 16]);
                unsigned b1 = ld32h(&Ks[nb + kt * 16 + 8]);
                mma_f16(s[nt], qa[kt], b0, b1);
            }
        }

        // ---- Online softmax ----
        float mx0 = -1e30f, mx1 = -1e30f;
#pragma unroll
        for (int nt = 0; nt < 8; ++nt) {
            mx0 = fmaxf(mx0, fmaxf(s[nt][0], s[nt][1]));
            mx1 = fmaxf(mx1, fmaxf(s[nt][2], s[nt][3]));
        }
        mx0 = fmaxf(mx0, __shfl_xor_sync(0xFFFFFFFFu, mx0, 1));
        mx0 = fmaxf(mx0, __shfl_xor_sync(0xFFFFFFFFu, mx0, 2));
        mx1 = fmaxf(mx1, __shfl_xor_sync(0xFFFFFFFFu, mx1, 1));
        mx1 = fmaxf(mx1, __shfl_xor_sync(0xFFFFFFFFu, mx1, 2));

        float nm0 = fmaxf(m0, mx0 * scale);
        float nm1 = fmaxf(m1, mx1 * scale);
        float corr0 = __expf(m0 - nm0);
        float corr1 = __expf(m1 - nm1);

        float sum0 = 0.f, sum1 = 0.f;
#pragma unroll
        for (int nt = 0; nt < 8; ++nt) {
            s[nt][0] = __expf(s[nt][0] * scale - nm0);
            s[nt][1] = __expf(s[nt][1] * scale - nm0);
            s[nt][2] = __expf(s[nt][2] * scale - nm1);
            s[nt][3] = __expf(s[nt][3] * scale - nm1);
            sum0 += s[nt][0] + s[nt][1];
            sum1 += s[nt][2] + s[nt][3];
        }
        sum0 += __shfl_xor_sync(0xFFFFFFFFu, sum0, 1);
        sum0 += __shfl_xor_sync(0xFFFFFFFFu, sum0, 2);
        sum1 += __shfl_xor_sync(0xFFFFFFFFu, sum1, 1);
        sum1 += __shfl_xor_sync(0xFFFFFFFFu, sum1, 2);

        l0 = l0 * corr0 + sum0;
        l1 = l1 * corr1 + sum1;
        m0 = nm0;
        m1 = nm1;

#pragma unroll
        for (int nt = 0; nt < 16; ++nt) {
            o[nt][0] *= corr0; o[nt][1] *= corr0;
            o[nt][2] *= corr1; o[nt][3] *= corr1;
        }

        // ---- P -> smem fp16 (warp-local rows) ----
#pragma unroll
        for (int nt = 0; nt < 8; ++nt) {
            int pc = nt * 8 + 2 * qc;
            *(__half2*)&Ps[prow * PSH + pc] = __floats2half2_rn(s[nt][0], s[nt][1]);
            *(__half2*)&Ps[(prow + 8) * PSH + pc] = __floats2half2_rn(s[nt][2], s[nt][3]);
        }
        __syncwarp();

        // ---- O += P @ V (Vt d-major: each B-frag = one LDS.32) ----
#pragma unroll
        for (int kt = 0; kt < 4; ++kt) {
            unsigned a[4];
            int kc = kt * 16 + 2 * qc;
            a[0] = ld32h(&Ps[prow * PSH + kc]);
            a[1] = ld32h(&Ps[(prow + 8) * PSH + kc]);
            a[2] = ld32h(&Ps[prow * PSH + kc + 8]);
            a[3] = ld32h(&Ps[(prow + 8) * PSH + kc + 8]);
#pragma unroll
            for (int nt = 0; nt < 16; ++nt) {
                const int nb = (nt * 8 + r0) * VSH + kt * 16 + 2 * qc;
                unsigned b0 = ld32h(&Vs[nb]);
                unsigned b1 = ld32h(&Vs[nb + 8]);
                mma_f16(o[nt], a, b0, b1);
            }
        }
    }

    // ---- Epilogue: normalize, fp16 store ----
    float inv0 = 1.f / l0, inv1 = 1.f / l1;
    int grow = qb * 64 + warp * 16 + r0;
#pragma unroll
    for (int nt = 0; nt < 16; ++nt) {
        int col = h * HDIM + nt * 8 + 2 * qc;
        *(__half2*)&O[(size_t)grow * DIM + col] =
            __floats2half2_rn(o[nt][0] * inv0, o[nt][1] * inv0);
        *(__half2*)&O[(size_t)(grow + 8) * DIM + col] =
            __floats2half2_rn(o[nt][2] * inv1, o[nt][3] * inv1);
    }
}

// ---------------------------------------------------------------------------
// Launch
// ---------------------------------------------------------------------------
extern "C" void kernel_launch(void* const* d_in, const int* in_sizes, int n_in,
                              void* d_out, int out_size)
{
    const float* x     = (const float*)d_in[0];
    const float* freqs = (const float*)d_in[1];
    const float* Wq    = (const float*)d_in[2];
    const float* bq    = (const float*)d_in[3];
    const float* Wk    = (const float*)d_in[4];
    const float* bk    = (const float*)d_in[5];
    const float* Wv    = (const float*)d_in[6];
    const float* bv    = (const float*)d_in[7];
    const float* Wo    = (const float*)d_in[8];
    const float* bo    = (const float*)d_in[9];
    const float* gq    = (const float*)d_in[10];
    const float* gk    = (const float*)d_in[11];
    float* out = (float*)d_out;

    __half *xh, *qh, *kh, *vh, *attnh, *wqh, *wkh, *wvh, *woh, *vt;
    cudaGetSymbolAddress((void**)&xh,    g_xh);
    cudaGetSymbolAddress((void**)&qh,    g_qh);
    cudaGetSymbolAddress((void**)&kh,    g_kh);
    cudaGetSymbolAddress((void**)&vh,    g_vh);
    cudaGetSymbolAddress((void**)&attnh, g_attnh);
    cudaGetSymbolAddress((void**)&wqh,   g_wqh);
    cudaGetSymbolAddress((void**)&wkh,   g_wkh);
    cudaGetSymbolAddress((void**)&wvh,   g_wvh);
    cudaGetSymbolAddress((void**)&woh,   g_woh);
    cudaGetSymbolAddress((void**)&vt,    g_vt);

    cudaFuncSetAttribute(flash_h_kernel,
                         cudaFuncAttributeMaxDynamicSharedMemorySize, FA_SMEM_BYTES);

    // Prep: trig + fp16 conversion (single fused launch).
    trig_kernel<<<(SEQ * 64 + 255) / 256, 256>>>(freqs);
    to_half_all_kernel<<<dim3(SEQ * DIM / 4 / 256, 5), 256>>>(x, Wq, Wk, Wv, Wo);

    // Fused Q/K/V projection (fp16 in/out).
    dim3 qkv_grid(DIM / 128, SEQ / 128, 3);
    gemm_h_kernel<1><<<qkv_grid, 256>>>(
        xh, wqh, wkh, wvh, bq, bk, bv, qh, kh, vh);

    // RMSNorm+RoPE (q,k) and V transpose in one launch.
    norm_and_transpose_kernel<<<dim3(SEQ, 3), 256>>>(qh, kh, gq, gk);

    // Flash attention: BQ=64, 4 warps (R7 measured-best config).
    flash_h_kernel<<<dim3(SEQ / 64, NHEADS), 128, FA_SMEM_BYTES>>>(qh, kh, vt, attnh);

    // Output projection (fp32 out).
    dim3 o_grid(DIM / 128, SEQ / 128, 1);
    gemm_h_kernel<0><<<o_grid, 256>>>(
        attnh, woh, woh, woh, bo, bo, bo, out, out, out);
}